// round 14
// baseline (speedup 1.0000x reference)
#include <cuda_runtime.h>
#include <math.h>

#define BATCH 2048
#define KSPLIT 7
#define KCHUNK 896   // 6272 / 7

__device__ float g_h1[BATCH*32*28*28];
__device__ float g_h2[BATCH*64*14*14];
__device__ float g_h3[BATCH*128*7*7];
__device__ float g_z [BATCH*64];
__device__ int   g_expert[BATCH];
__device__ float g_fc[BATCH*32*7*7];
__device__ float g_d1[BATCH*64*14*14];
__device__ float g_d2[BATCH*32*28*28];
__device__ float g_fcp[KSPLIT][BATCH][128];

// -------- encoder conv1: 1->32, 28x28, relu --------
__global__ void __launch_bounds__(256) k_enc1(const float* __restrict__ x,
                                              const float* __restrict__ w,
                                              const float* __restrict__ b) {
    __shared__ float s_in[30*30], s_w[32*9], s_b[32];
    const int n = blockIdx.x, tid = threadIdx.x;
    const float* __restrict__ xin = x + (size_t)n*784;
    for (int i = tid; i < 900; i += 256) {
        int y = i/30, xx = i - y*30;
        float v = 0.f;
        if (y >= 1 && y <= 28 && xx >= 1 && xx <= 28) v = xin[(y-1)*28 + (xx-1)];
        s_in[i] = v;
    }
    for (int i = tid; i < 288; i += 256) s_w[i] = w[i];
    if (tid < 32)  s_b[tid] = b[tid];
    __syncthreads();
    for (int p = tid; p < 784; p += 256) {
        const int oy = p/28, ox = p - oy*28;
        float in9[9];
        #pragma unroll
        for (int ky = 0; ky < 3; ky++)
            #pragma unroll
            for (int kx = 0; kx < 3; kx++)
                in9[ky*3+kx] = s_in[(oy+ky)*30 + ox + kx];
        #pragma unroll 4
        for (int oc = 0; oc < 32; oc++) {
            float a = s_b[oc];
            #pragma unroll
            for (int k = 0; k < 9; k++) a = fmaf(s_w[oc*9+k], in9[k], a);
            g_h1[((size_t)n*32 + oc)*784 + p] = fmaxf(a, 0.f);
        }
    }
}

// -------- encoder conv2: 32->64, stride2, 28->14, relu (2-oc v2) --------
__global__ void __launch_bounds__(256) k_enc2(const float* __restrict__ w,
                                              const float* __restrict__ b) {
    extern __shared__ float s[];                 // 16*900 floats
    const int n = blockIdx.x, tid = threadIdx.x;
    const float* __restrict__ hin = g_h1 + (size_t)n*32*784;
    const int ocp = tid & 31, g = tid >> 5;      // 32 oc-pairs x 8 regions
    const int q = g & 3, half = g >> 2;          // warp-uniform
    const int qy = (q >> 1)*7, qx = (q & 1)*7;
    const int r0 = half*4;
    const int oc0 = ocp, oc1 = ocp + 32;
    float acc0[28], acc1[28];
    const float bias0 = __ldg(b + oc0), bias1 = __ldg(b + oc1);
    #pragma unroll
    for (int i = 0; i < 28; i++) { acc0[i] = bias0; acc1[i] = bias1; }
    const float* __restrict__ wp0 = w + oc0*32*9;
    const float* __restrict__ wp1 = w + oc1*32*9;
    // precompute clamped row bases (warp-uniform)
    int rbase[4];
    #pragma unroll
    for (int rr = 0; rr < 4; rr++) {
        int row = qy + r0 + rr;
        int rowc = row < 14 ? row : 13;
        rbase[rr] = (2*rowc)*30 + 2*qx;
    }
    // weight double buffer
    float wc0[9], wc1[9], wn0[9], wn1[9];
    #pragma unroll
    for (int k = 0; k < 9; k++) { wc0[k] = __ldg(wp0 + k); wc1[k] = __ldg(wp1 + k); }
    for (int ch = 0; ch < 2; ch++) {
        const int icbase = ch*16;
        if (ch) __syncthreads();
        for (int i = tid; i < 16*900; i += 256) {
            int icl = i/900, rem = i - icl*900, y = rem/30, xx = rem - y*30;
            float v = 0.f;
            if (y >= 1 && y <= 28 && xx >= 1 && xx <= 28)
                v = hin[(icbase+icl)*784 + (y-1)*28 + (xx-1)];
            s[i] = v;
        }
        __syncthreads();
        for (int icl = 0; icl < 16; icl++) {
            const int icn = icbase + icl + 1;     // global next ic
            if (icn < 32) {
                #pragma unroll
                for (int k = 0; k < 9; k++) {
                    wn0[k] = __ldg(wp0 + icn*9 + k);
                    wn1[k] = __ldg(wp1 + icn*9 + k);
                }
            }
            const float* sb2 = s + icl*900;
            #pragma unroll
            for (int rr = 0; rr < 4; rr++) {
                const float* sp = sb2 + rbase[rr];
                #pragma unroll
                for (int c = 0; c < 7; c++) {
                    const float* p = sp + 2*c;
                    const float i0 = p[0],  i1 = p[1],  i2 = p[2];
                    const float i3 = p[30], i4 = p[31], i5 = p[32];
                    const float i6 = p[60], i7 = p[61], i8 = p[62];
                    float a0 = acc0[rr*7+c];
                    a0 = fmaf(wc0[0], i0, a0); a0 = fmaf(wc0[1], i1, a0); a0 = fmaf(wc0[2], i2, a0);
                    a0 = fmaf(wc0[3], i3, a0); a0 = fmaf(wc0[4], i4, a0); a0 = fmaf(wc0[5], i5, a0);
                    a0 = fmaf(wc0[6], i6, a0); a0 = fmaf(wc0[7], i7, a0); a0 = fmaf(wc0[8], i8, a0);
                    acc0[rr*7+c] = a0;
                    float a1 = acc1[rr*7+c];
                    a1 = fmaf(wc1[0], i0, a1); a1 = fmaf(wc1[1], i1, a1); a1 = fmaf(wc1[2], i2, a1);
                    a1 = fmaf(wc1[3], i3, a1); a1 = fmaf(wc1[4], i4, a1); a1 = fmaf(wc1[5], i5, a1);
                    a1 = fmaf(wc1[6], i6, a1); a1 = fmaf(wc1[7], i7, a1); a1 = fmaf(wc1[8], i8, a1);
                    acc1[rr*7+c] = a1;
                }
            }
            #pragma unroll
            for (int k = 0; k < 9; k++) { wc0[k] = wn0[k]; wc1[k] = wn1[k]; }
        }
    }
    float* __restrict__ op0 = g_h2 + ((size_t)n*64 + oc0)*196;
    float* __restrict__ op1 = g_h2 + ((size_t)n*64 + oc1)*196;
    #pragma unroll
    for (int rr = 0; rr < 4; rr++) {
        const int row = qy + r0 + rr;
        if (row < 14) {
            #pragma unroll
            for (int c = 0; c < 7; c++) {
                op0[row*14 + qx + c] = fmaxf(acc0[rr*7+c], 0.f);
                op1[row*14 + qx + c] = fmaxf(acc1[rr*7+c], 0.f);
            }
        }
    }
}

// -------- encoder conv3: 64->128, stride2, 14->7, relu (ic-chunked x2) --------
__global__ void __launch_bounds__(128) k_enc3(const float* __restrict__ w,
                                              const float* __restrict__ b) {
    extern __shared__ float s[];                 // 32*256 floats
    const int n = blockIdx.x, tid = threadIdx.x;
    const float* __restrict__ hin = g_h2 + (size_t)n*64*196;
    const int oc = tid;
    float acc[49];
    const float bias = __ldg(b + oc);
    #pragma unroll
    for (int i = 0; i < 49; i++) acc[i] = bias;
    const float* __restrict__ wp = w + oc*64*9;
    for (int ch = 0; ch < 2; ch++) {
        const int icbase = ch*32;
        if (ch) __syncthreads();
        for (int i = tid; i < 32*256; i += 128) {
            int icl = i >> 8, rem = i & 255, y = rem >> 4, xx = rem & 15;
            float v = 0.f;
            if (y >= 1 && y <= 14 && xx >= 1 && xx <= 14)
                v = hin[(icbase+icl)*196 + (y-1)*14 + (xx-1)];
            s[i] = v;
        }
        __syncthreads();
        for (int icl = 0; icl < 32; icl++) {
            float wr[9];
            #pragma unroll
            for (int k = 0; k < 9; k++) wr[k] = __ldg(wp + (icbase+icl)*9 + k);
            const float* sp = s + icl*256;
            #pragma unroll
            for (int r = 0; r < 7; r++)
                #pragma unroll
                for (int c = 0; c < 7; c++) {
                    const float* p = sp + (2*r)*16 + 2*c;
                    float a = acc[r*7+c];
                    a = fmaf(wr[0], p[0],  a); a = fmaf(wr[1], p[1],  a); a = fmaf(wr[2], p[2],  a);
                    a = fmaf(wr[3], p[16], a); a = fmaf(wr[4], p[17], a); a = fmaf(wr[5], p[18], a);
                    a = fmaf(wr[6], p[32], a); a = fmaf(wr[7], p[33], a); a = fmaf(wr[8], p[34], a);
                    acc[r*7+c] = a;
                }
        }
    }
    float* __restrict__ op = g_h3 + ((size_t)n*128 + oc)*49;
    #pragma unroll
    for (int i = 0; i < 49; i++) op[i] = fmaxf(acc[i], 0.f);
}

// -------- fc partial: split-K over 7 chunks --------
__global__ void __launch_bounds__(256) k_fc_part(const float* __restrict__ w_mu,
                                                 const float* __restrict__ w_lv) {
    __shared__ float As[16][33];
    __shared__ float Bs[32][128];
    const int mblk = blockIdx.x & 127;
    const int split = blockIdx.x >> 7;
    const int n0 = mblk*16;
    const int kbase = split*KCHUNK;
    const int tid = threadIdx.x;
    const int tx = tid & 31, ty = tid >> 5;
    float acc[2][4] = {{0.f,0.f,0.f,0.f},{0.f,0.f,0.f,0.f}};
    for (int k0 = kbase; k0 < kbase + KCHUNK; k0 += 32) {
        for (int i = tid; i < 512; i += 256) {
            int ss = i >> 5, kk = i & 31;
            As[ss][kk] = g_h3[(size_t)(n0+ss)*6272 + k0 + kk];
        }
        for (int i = tid; i < 4096; i += 256) {
            int kk = i >> 7, o = i & 127;
            Bs[kk][o] = (o < 64) ? __ldg(w_mu + (size_t)(k0+kk)*64 + o)
                                 : __ldg(w_lv + (size_t)(k0+kk)*64 + (o-64));
        }
        __syncthreads();
        #pragma unroll
        for (int kk = 0; kk < 32; kk++) {
            float b0 = Bs[kk][tx*4+0], b1 = Bs[kk][tx*4+1];
            float b2 = Bs[kk][tx*4+2], b3 = Bs[kk][tx*4+3];
            float a0 = As[ty*2+0][kk], a1 = As[ty*2+1][kk];
            acc[0][0]=fmaf(a0,b0,acc[0][0]); acc[0][1]=fmaf(a0,b1,acc[0][1]);
            acc[0][2]=fmaf(a0,b2,acc[0][2]); acc[0][3]=fmaf(a0,b3,acc[0][3]);
            acc[1][0]=fmaf(a1,b0,acc[1][0]); acc[1][1]=fmaf(a1,b1,acc[1][1]);
            acc[1][2]=fmaf(a1,b2,acc[1][2]); acc[1][3]=fmaf(a1,b3,acc[1][3]);
        }
        __syncthreads();
    }
    #pragma unroll
    for (int i = 0; i < 2; i++) {
        const int nn = n0 + ty*2 + i;
        #pragma unroll
        for (int j = 0; j < 4; j++)
            g_fcp[split][nn][tx*4+j] = acc[i][j];
    }
}

// -------- fc reduce --------
__global__ void __launch_bounds__(256) k_fc_red(const float* __restrict__ b_mu,
                                                const float* __restrict__ b_lv,
                                                float* __restrict__ out_mu,
                                                float* __restrict__ out_lv) {
    const int idx = blockIdx.x*256 + threadIdx.x;
    const int n = idx >> 7, o = idx & 127;
    float a = 0.f;
    #pragma unroll
    for (int s2 = 0; s2 < KSPLIT; s2++) a += g_fcp[s2][n][o];
    if (o < 64) out_mu[n*64 + o]      = a + __ldg(b_mu + o);
    else        out_lv[n*64 + (o-64)] = a + __ldg(b_lv + (o-64));
}

// -------- gating --------
__global__ void __launch_bounds__(128) k_gate(
        const float* __restrict__ gw1, const float* __restrict__ gb1,
        const float* __restrict__ gw2, const float* __restrict__ gb2,
        const float* __restrict__ gw3, const float* __restrict__ gb3,
        const float* __restrict__ eps,
        const float* __restrict__ mu_o, const float* __restrict__ lv_o,
        float* __restrict__ logit_o, float* __restrict__ prob_o) {
    __shared__ float sw1[64*64], sw2[64*32], sw3[32*8];
    __shared__ float sb1[64], sb2[32], sb3[8];
    __shared__ float sz[4][64], sh1[4][64], sh2[4][32], sh3[4][8];
    const int tid = threadIdx.x;
    for (int i = tid; i < 4096; i += 128) sw1[i] = gw1[i];
    for (int i = tid; i < 2048; i += 128) sw2[i] = gw2[i];
    for (int i = tid; i < 256;  i += 128) sw3[i] = gw3[i];
    if (tid < 64) sb1[tid] = gb1[tid];
    if (tid < 32) sb2[tid] = gb2[tid];
    if (tid < 8)  sb3[tid] = gb3[tid];
    __syncthreads();
    const int wid = tid >> 5, lane = tid & 31;
    const int n = blockIdx.x*4 + wid;
    for (int o = lane; o < 64; o += 32) {
        float mu = mu_o[n*64+o], lv = lv_o[n*64+o];
        float z = mu + eps[n*64+o]*expf(0.5f*lv);
        g_z[n*64+o] = z; sz[wid][o] = z;
    }
    __syncwarp();
    for (int o = lane; o < 64; o += 32) {
        float a = sb1[o];
        #pragma unroll 8
        for (int k = 0; k < 64; k++) a = fmaf(sz[wid][k], sw1[k*64+o], a);
        sh1[wid][o] = fmaxf(a, 0.f);
    }
    __syncwarp();
    {
        float a = sb2[lane];
        #pragma unroll 8
        for (int k = 0; k < 64; k++) a = fmaf(sh1[wid][k], sw2[k*32+lane], a);
        sh2[wid][lane] = fmaxf(a, 0.f);
    }
    __syncwarp();
    if (lane < 8) {
        float a = sb3[lane];
        #pragma unroll 8
        for (int k = 0; k < 32; k++) a = fmaf(sh2[wid][k], sw3[k*8+lane], a);
        sh3[wid][lane] = a;
    }
    __syncwarp();
    if (lane == 0) {
        float m = sh3[wid][0];
        #pragma unroll
        for (int j = 1; j < 8; j++) m = fmaxf(m, sh3[wid][j]);
        float ex[8], ssum = 0.f;
        #pragma unroll
        for (int j = 0; j < 8; j++) { ex[j] = expf(sh3[wid][j]-m); ssum += ex[j]; }
        const float inv = 1.f/ssum;
        int best = 0; float bp = -1.f;
        #pragma unroll
        for (int j = 0; j < 8; j++) {
            float pp = ex[j]*inv;
            prob_o[n*8+j]  = pp;
            logit_o[n*8+j] = logf(pp + 1e-8f);
            if (pp > bp) { bp = pp; best = j; }
        }
        g_expert[n] = best;
    }
}

// -------- decoder fc --------
__global__ void __launch_bounds__(256) k_dfc(const float* __restrict__ fcw,
                                             const float* __restrict__ fcb) {
    __shared__ float sz[64];
    const int n = blockIdx.x, tid = threadIdx.x;
    const int e = g_expert[n];
    if (tid < 64) sz[tid] = g_z[n*64+tid];
    __syncthreads();
    const float* __restrict__ W  = fcw + (size_t)e*64*1568;
    const float* __restrict__ bb = fcb + (size_t)e*1568;
    for (int o = tid; o < 1568; o += 256) {
        float a = __ldg(bb + o);
        #pragma unroll 8
        for (int k = 0; k < 64; k++) a = fmaf(sz[k], __ldg(W + k*1568 + o), a);
        g_fc[(size_t)n*1568 + o] = a;
    }
}

// -------- decoder conv1 + fused up2 (scalar R6) --------
__global__ void __launch_bounds__(256) k_dec1(const float* __restrict__ w,
                                              const float* __restrict__ b) {
    __shared__ float s[32*81];
    const int n = blockIdx.x, tid = threadIdx.x;
    const int e = g_expert[n];
    const float* __restrict__ src = g_fc + (size_t)n*1568;
    for (int i = tid; i < 32*81; i += 256) {
        int ic = i/81, rem = i - ic*81, y = rem/9, xx = rem - y*9;
        float v = 0.f;
        if (y >= 1 && y <= 7 && xx >= 1 && xx <= 7) v = src[ic*49 + (y-1)*7 + (xx-1)];
        s[i] = v;
    }
    __syncthreads();
    const int oc = tid & 63, q = tid >> 6;
    const int py = q >> 1, px = q & 1;
    float acc[49];
    const float bias = __ldg(b + e*64 + oc);
    #pragma unroll
    for (int i = 0; i < 49; i++) acc[i] = bias;
    const float* __restrict__ wp = w + ((size_t)e*64 + oc)*32*9;
    for (int ic = 0; ic < 32; ic++) {
        float wr[9];
        #pragma unroll
        for (int k = 0; k < 9; k++) wr[k] = __ldg(wp + ic*9 + k);
        float v0[3], v1[3];
        #pragma unroll
        for (int kx = 0; kx < 3; kx++) {
            v0[kx] = py ? wr[kx]+wr[3+kx] : wr[kx];
            v1[kx] = py ? wr[6+kx]        : wr[3+kx]+wr[6+kx];
        }
        const float e00 = px ? v0[0]+v0[1] : v0[0];
        const float e01 = px ? v0[2]       : v0[1]+v0[2];
        const float e10 = px ? v1[0]+v1[1] : v1[0];
        const float e11 = px ? v1[2]       : v1[1]+v1[2];
        const float* sp = s + ic*81 + py*9 + px;
        #pragma unroll
        for (int r = 0; r < 7; r++) {
            const float* rp = sp + r*9;
            #pragma unroll
            for (int c = 0; c < 7; c++) {
                float a = acc[r*7+c];
                a = fmaf(e00, rp[c],    a);
                a = fmaf(e01, rp[c+1],  a);
                a = fmaf(e10, rp[9+c],  a);
                a = fmaf(e11, rp[10+c], a);
                acc[r*7+c] = a;
            }
        }
    }
    float* __restrict__ op = g_d1 + ((size_t)n*64 + oc)*196;
    #pragma unroll
    for (int r = 0; r < 7; r++)
        #pragma unroll
        for (int c = 0; c < 7; c++) {
            float a = acc[r*7+c];
            op[(2*r+py)*14 + (2*c+px)] = a > 0.f ? a : expm1f(a);
        }
}

// -------- decoder conv2 + fused up2 (scalar R6, ic-chunked x2) --------
__global__ void __launch_bounds__(256) k_dec2(const float* __restrict__ w,
                                              const float* __restrict__ b) {
    extern __shared__ float s[];                 // 32*256 input + 32*9*32 weights
    float* ws = s + 32*256;
    const int n = blockIdx.x, tid = threadIdx.x;
    const int e = g_expert[n];
    const float* __restrict__ src  = g_d1 + (size_t)n*64*196;
    const float* __restrict__ wsrc = w + (size_t)e*32*64*9;
    const int oc = tid & 31, g = tid >> 5;
    const int q = g & 3, rh = g >> 2;
    const int py = q >> 1, px = q & 1;
    float acc[98];
    const float bias = __ldg(b + e*32 + oc);
    #pragma unroll
    for (int i = 0; i < 98; i++) acc[i] = bias;
    for (int ch = 0; ch < 2; ch++) {
        const int icbase = ch*32;
        if (ch) __syncthreads();
        for (int i = tid; i < 32*256; i += 256) {
            int icl = i >> 8, rem = i & 255, y = rem >> 4, xx = rem & 15;
            float v = 0.f;
            if (y >= 1 && y <= 14 && xx >= 1 && xx <= 14)
                v = src[(icbase+icl)*196 + (y-1)*14 + (xx-1)];
            s[i] = v;
        }
        for (int i = tid; i < 32*32*9; i += 256) {
            int ocl = i/288, rem = i - ocl*288, icl = rem/9, k = rem - icl*9;
            ws[(icl*9+k)*32 + ocl] = wsrc[ocl*576 + (icbase+icl)*9 + k];
        }
        __syncthreads();
        for (int icl = 0; icl < 32; icl++) {
            float wr[9];
            #pragma unroll
            for (int k = 0; k < 9; k++) wr[k] = ws[(icl*9+k)*32 + oc];
            float v0[3], v1[3];
            #pragma unroll
            for (int kx = 0; kx < 3; kx++) {
                v0[kx] = py ? wr[kx]+wr[3+kx] : wr[kx];
                v1[kx] = py ? wr[6+kx]        : wr[3+kx]+wr[6+kx];
            }
            const float e00 = px ? v0[0]+v0[1] : v0[0];
            const float e01 = px ? v0[2]       : v0[1]+v0[2];
            const float e10 = px ? v1[0]+v1[1] : v1[0];
            const float e11 = px ? v1[2]       : v1[1]+v1[2];
            const float* sp = s + icl*256 + (rh*7 + py)*16 + px;
            #pragma unroll
            for (int rr = 0; rr < 7; rr++) {
                const float* rp = sp + rr*16;
                #pragma unroll
                for (int c = 0; c < 14; c++) {
                    float a = acc[rr*14+c];
                    a = fmaf(e00, rp[c],    a);
                    a = fmaf(e01, rp[c+1],  a);
                    a = fmaf(e10, rp[16+c], a);
                    a = fmaf(e11, rp[17+c], a);
                    acc[rr*14+c] = a;
                }
            }
        }
    }
    float* __restrict__ op = g_d2 + ((size_t)n*32 + oc)*784;
    #pragma unroll
    for (int rr = 0; rr < 7; rr++) {
        const int oy = 2*(rh*7+rr) + py;
        #pragma unroll
        for (int c = 0; c < 14; c++) {
            float a = acc[rr*14+c];
            op[oy*28 + 2*c + px] = a > 0.f ? a : expm1f(a);
        }
    }
}

// -------- decoder conv3: 32->1, 28x28, sigmoid (ic-chunked smem) --------
__global__ void __launch_bounds__(256) k_dec3(const float* __restrict__ w,
                                              const float* __restrict__ b,
                                              float* __restrict__ rec) {
    __shared__ float sw[32*9];
    __shared__ float sbb;
    __shared__ float st[8*900];
    const int n = blockIdx.x, tid = threadIdx.x;
    const int e = g_expert[n];
    for (int i = tid; i < 288; i += 256) sw[i] = w[e*288 + i];
    if (tid == 0)  sbb = b[e];
    __syncthreads();
    const float* __restrict__ src = g_d2 + (size_t)n*32*784;
    int oy[4], ox[4];
    float acc[4];
    #pragma unroll
    for (int it = 0; it < 4; it++) {
        int p = tid + 256*it;
        oy[it] = p/28; ox[it] = p - oy[it]*28;
        acc[it] = sbb;
    }
    for (int ch = 0; ch < 4; ch++) {
        const int icb = ch*8;
        if (ch) __syncthreads();
        for (int i = tid; i < 8*900; i += 256) {
            int icl = i/900, rem = i - icl*900, y = rem/30, xx = rem - y*30;
            float v = 0.f;
            if (y >= 1 && y <= 28 && xx >= 1 && xx <= 28)
                v = src[(icb+icl)*784 + (y-1)*28 + (xx-1)];
            st[i] = v;
        }
        __syncthreads();
        for (int icl = 0; icl < 8; icl++) {
            const float* wr = sw + (icb+icl)*9;
            const float w0 = wr[0], w1 = wr[1], w2 = wr[2];
            const float w3 = wr[3], w4 = wr[4], w5 = wr[5];
            const float w6 = wr[6], w7 = wr[7], w8 = wr[8];
            const float* tb = st + icl*900;
            #pragma unroll
            for (int it = 0; it < 4; it++) {
                if (it == 3 && tid >= 16) break;
                const float* sp = tb + oy[it]*30 + ox[it];
                float a = acc[it];
                a = fmaf(w0, sp[0],  a); a = fmaf(w1, sp[1],  a); a = fmaf(w2, sp[2],  a);
                a = fmaf(w3, sp[30], a); a = fmaf(w4, sp[31], a); a = fmaf(w5, sp[32], a);
                a = fmaf(w6, sp[60], a); a = fmaf(w7, sp[61], a); a = fmaf(w8, sp[62], a);
                acc[it] = a;
            }
        }
    }
    #pragma unroll
    for (int it = 0; it < 4; it++) {
        int p = tid + 256*it;
        if (p < 784)
            rec[(size_t)n*784 + p] = 1.f/(1.f + expf(-acc[it]));
    }
}

extern "C" void kernel_launch(void* const* d_in, const int* in_sizes, int n_in,
                              void* d_out, int out_size) {
    const float* x      = (const float*)d_in[0];
    const float* eps    = (const float*)d_in[1];
    const float* enc_w1 = (const float*)d_in[2];
    const float* enc_b1 = (const float*)d_in[3];
    const float* enc_w2 = (const float*)d_in[4];
    const float* enc_b2 = (const float*)d_in[5];
    const float* enc_w3 = (const float*)d_in[6];
    const float* enc_b3 = (const float*)d_in[7];
    const float* w_mu   = (const float*)d_in[8];
    const float* b_mu   = (const float*)d_in[9];
    const float* w_lv   = (const float*)d_in[10];
    const float* b_lv   = (const float*)d_in[11];
    const float* gw1    = (const float*)d_in[12];
    const float* gb1    = (const float*)d_in[13];
    const float* gw2    = (const float*)d_in[14];
    const float* gb2    = (const float*)d_in[15];
    const float* gw3    = (const float*)d_in[16];
    const float* gb3    = (const float*)d_in[17];
    const float* d_fc_w = (const float*)d_in[18];
    const float* d_fc_b = (const float*)d_in[19];
    const float* d_w1   = (const float*)d_in[20];
    const float* d_b1   = (const float*)d_in[21];
    const float* d_w2   = (const float*)d_in[22];
    const float* d_b2   = (const float*)d_in[23];
    const float* d_w3   = (const float*)d_in[24];
    const float* d_b3   = (const float*)d_in[25];

    float* out        = (float*)d_out;
    float* out_rec    = out;
    float* out_mu     = out + 2048*784;
    float* out_lv     = out_mu + 2048*64;
    float* out_logits = out_lv + 2048*64;
    float* out_probs  = out_logits + 2048*8;

    static int attr_done = 0;
    if (!attr_done) {
        cudaFuncSetAttribute(k_enc2, cudaFuncAttributeMaxDynamicSharedMemorySize, 16*900*4);
        cudaFuncSetAttribute(k_enc3, cudaFuncAttributeMaxDynamicSharedMemorySize, 32*256*4);
        cudaFuncSetAttribute(k_dec2, cudaFuncAttributeMaxDynamicSharedMemorySize, (32*256 + 32*9*32)*4);
        attr_done = 1;
    }

    k_enc1<<<BATCH, 256>>>(x, enc_w1, enc_b1);
    k_enc2<<<BATCH, 256, 16*900*4>>>(enc_w2, enc_b2);
    k_enc3<<<BATCH, 128, 32*256*4>>>(enc_w3, enc_b3);
    k_fc_part<<<128*KSPLIT, 256>>>(w_mu, w_lv);
    k_fc_red <<<BATCH*128/256, 256>>>(b_mu, b_lv, out_mu, out_lv);
    k_gate<<<BATCH/4, 128>>>(gw1, gb1, gw2, gb2, gw3, gb3, eps,
                             out_mu, out_lv, out_logits, out_probs);
    k_dfc <<<BATCH, 256>>>(d_fc_w, d_fc_b);
    k_dec1<<<BATCH, 256>>>(d_w1, d_b1);
    k_dec2<<<BATCH, 256, (32*256 + 32*9*32)*4>>>(d_w2, d_b2);
    k_dec3<<<BATCH, 256>>>(d_w3, d_b3, out_rec);
}

// round 15
// speedup vs baseline: 1.1406x; 1.1406x over previous
#include <cuda_runtime.h>
#include <math.h>

#define BATCH 2048
#define KSPLIT 7
#define KCHUNK 896   // 6272 / 7

__device__ float g_h1[BATCH*32*28*28];
__device__ float g_h2[BATCH*64*14*14];
__device__ float g_h3[BATCH*128*7*7];
__device__ float g_z [BATCH*64];
__device__ int   g_expert[BATCH];
__device__ float g_fc[BATCH*32*7*7];
__device__ float g_d1[BATCH*64*14*14];
__device__ float g_d2[BATCH*32*28*28];
__device__ float g_fcp[KSPLIT][BATCH][128];

// -------- encoder conv1: 1->32, 28x28, relu --------
__global__ void __launch_bounds__(256) k_enc1(const float* __restrict__ x,
                                              const float* __restrict__ w,
                                              const float* __restrict__ b) {
    __shared__ float s_in[30*30], s_w[32*9], s_b[32];
    const int n = blockIdx.x, tid = threadIdx.x;
    const float* __restrict__ xin = x + (size_t)n*784;
    for (int i = tid; i < 900; i += 256) {
        int y = i/30, xx = i - y*30;
        float v = 0.f;
        if (y >= 1 && y <= 28 && xx >= 1 && xx <= 28) v = xin[(y-1)*28 + (xx-1)];
        s_in[i] = v;
    }
    for (int i = tid; i < 288; i += 256) s_w[i] = w[i];
    if (tid < 32)  s_b[tid] = b[tid];
    __syncthreads();
    for (int p = tid; p < 784; p += 256) {
        const int oy = p/28, ox = p - oy*28;
        float in9[9];
        #pragma unroll
        for (int ky = 0; ky < 3; ky++)
            #pragma unroll
            for (int kx = 0; kx < 3; kx++)
                in9[ky*3+kx] = s_in[(oy+ky)*30 + ox + kx];
        #pragma unroll 4
        for (int oc = 0; oc < 32; oc++) {
            float a = s_b[oc];
            #pragma unroll
            for (int k = 0; k < 9; k++) a = fmaf(s_w[oc*9+k], in9[k], a);
            g_h1[((size_t)n*32 + oc)*784 + p] = fmaxf(a, 0.f);
        }
    }
}

// -------- encoder conv2: 32->64, stride2, 28->14, relu (ic-chunked x2) --------
__global__ void __launch_bounds__(256) k_enc2(const float* __restrict__ w,
                                              const float* __restrict__ b) {
    extern __shared__ float s[];                 // 16*900 floats
    const int n = blockIdx.x, tid = threadIdx.x;
    const float* __restrict__ hin = g_h1 + (size_t)n*32*784;
    const int oc = tid & 63, q = tid >> 6;
    const int qy = (q >> 1)*7, qx = (q & 1)*7;
    float acc[49];
    const float bias = __ldg(b + oc);
    #pragma unroll
    for (int i = 0; i < 49; i++) acc[i] = bias;
    const float* __restrict__ wp = w + oc*32*9;
    for (int ch = 0; ch < 2; ch++) {
        const int icbase = ch*16;
        if (ch) __syncthreads();
        for (int i = tid; i < 16*900; i += 256) {
            int icl = i/900, rem = i - icl*900, y = rem/30, xx = rem - y*30;
            float v = 0.f;
            if (y >= 1 && y <= 28 && xx >= 1 && xx <= 28)
                v = hin[(icbase+icl)*784 + (y-1)*28 + (xx-1)];
            s[i] = v;
        }
        __syncthreads();
        for (int icl = 0; icl < 16; icl++) {
            float wr[9];
            #pragma unroll
            for (int k = 0; k < 9; k++) wr[k] = __ldg(wp + (icbase+icl)*9 + k);
            const float* sp = s + icl*900 + (2*qy)*30 + 2*qx;
            #pragma unroll
            for (int r = 0; r < 7; r++)
                #pragma unroll
                for (int c = 0; c < 7; c++) {
                    const float* p = sp + (2*r)*30 + 2*c;
                    float a = acc[r*7+c];
                    a = fmaf(wr[0], p[0],  a); a = fmaf(wr[1], p[1],  a); a = fmaf(wr[2], p[2],  a);
                    a = fmaf(wr[3], p[30], a); a = fmaf(wr[4], p[31], a); a = fmaf(wr[5], p[32], a);
                    a = fmaf(wr[6], p[60], a); a = fmaf(wr[7], p[61], a); a = fmaf(wr[8], p[62], a);
                    acc[r*7+c] = a;
                }
        }
    }
    float* __restrict__ op = g_h2 + ((size_t)n*64 + oc)*196;
    #pragma unroll
    for (int r = 0; r < 7; r++)
        #pragma unroll
        for (int c = 0; c < 7; c++)
            op[(qy+r)*14 + (qx+c)] = fmaxf(acc[r*7+c], 0.f);
}

// -------- encoder conv3: 64->128, stride2, 14->7, relu (ic-chunked x2) --------
__global__ void __launch_bounds__(128) k_enc3(const float* __restrict__ w,
                                              const float* __restrict__ b) {
    extern __shared__ float s[];                 // 32*256 floats
    const int n = blockIdx.x, tid = threadIdx.x;
    const float* __restrict__ hin = g_h2 + (size_t)n*64*196;
    const int oc = tid;
    float acc[49];
    const float bias = __ldg(b + oc);
    #pragma unroll
    for (int i = 0; i < 49; i++) acc[i] = bias;
    const float* __restrict__ wp = w + oc*64*9;
    for (int ch = 0; ch < 2; ch++) {
        const int icbase = ch*32;
        if (ch) __syncthreads();
        for (int i = tid; i < 32*256; i += 128) {
            int icl = i >> 8, rem = i & 255, y = rem >> 4, xx = rem & 15;
            float v = 0.f;
            if (y >= 1 && y <= 14 && xx >= 1 && xx <= 14)
                v = hin[(icbase+icl)*196 + (y-1)*14 + (xx-1)];
            s[i] = v;
        }
        __syncthreads();
        for (int icl = 0; icl < 32; icl++) {
            float wr[9];
            #pragma unroll
            for (int k = 0; k < 9; k++) wr[k] = __ldg(wp + (icbase+icl)*9 + k);
            const float* sp = s + icl*256;
            #pragma unroll
            for (int r = 0; r < 7; r++)
                #pragma unroll
                for (int c = 0; c < 7; c++) {
                    const float* p = sp + (2*r)*16 + 2*c;
                    float a = acc[r*7+c];
                    a = fmaf(wr[0], p[0],  a); a = fmaf(wr[1], p[1],  a); a = fmaf(wr[2], p[2],  a);
                    a = fmaf(wr[3], p[16], a); a = fmaf(wr[4], p[17], a); a = fmaf(wr[5], p[18], a);
                    a = fmaf(wr[6], p[32], a); a = fmaf(wr[7], p[33], a); a = fmaf(wr[8], p[34], a);
                    acc[r*7+c] = a;
                }
        }
    }
    float* __restrict__ op = g_h3 + ((size_t)n*128 + oc)*49;
    #pragma unroll
    for (int i = 0; i < 49; i++) op[i] = fmaxf(acc[i], 0.f);
}

// -------- fc partial: split-K over 7 chunks --------
__global__ void __launch_bounds__(256) k_fc_part(const float* __restrict__ w_mu,
                                                 const float* __restrict__ w_lv) {
    __shared__ float As[16][33];
    __shared__ float Bs[32][128];
    const int mblk = blockIdx.x & 127;
    const int split = blockIdx.x >> 7;
    const int n0 = mblk*16;
    const int kbase = split*KCHUNK;
    const int tid = threadIdx.x;
    const int tx = tid & 31, ty = tid >> 5;
    float acc[2][4] = {{0.f,0.f,0.f,0.f},{0.f,0.f,0.f,0.f}};
    for (int k0 = kbase; k0 < kbase + KCHUNK; k0 += 32) {
        for (int i = tid; i < 512; i += 256) {
            int ss = i >> 5, kk = i & 31;
            As[ss][kk] = g_h3[(size_t)(n0+ss)*6272 + k0 + kk];
        }
        for (int i = tid; i < 4096; i += 256) {
            int kk = i >> 7, o = i & 127;
            Bs[kk][o] = (o < 64) ? __ldg(w_mu + (size_t)(k0+kk)*64 + o)
                                 : __ldg(w_lv + (size_t)(k0+kk)*64 + (o-64));
        }
        __syncthreads();
        #pragma unroll
        for (int kk = 0; kk < 32; kk++) {
            float b0 = Bs[kk][tx*4+0], b1 = Bs[kk][tx*4+1];
            float b2 = Bs[kk][tx*4+2], b3 = Bs[kk][tx*4+3];
            float a0 = As[ty*2+0][kk], a1 = As[ty*2+1][kk];
            acc[0][0]=fmaf(a0,b0,acc[0][0]); acc[0][1]=fmaf(a0,b1,acc[0][1]);
            acc[0][2]=fmaf(a0,b2,acc[0][2]); acc[0][3]=fmaf(a0,b3,acc[0][3]);
            acc[1][0]=fmaf(a1,b0,acc[1][0]); acc[1][1]=fmaf(a1,b1,acc[1][1]);
            acc[1][2]=fmaf(a1,b2,acc[1][2]); acc[1][3]=fmaf(a1,b3,acc[1][3]);
        }
        __syncthreads();
    }
    #pragma unroll
    for (int i = 0; i < 2; i++) {
        const int nn = n0 + ty*2 + i;
        #pragma unroll
        for (int j = 0; j < 4; j++)
            g_fcp[split][nn][tx*4+j] = acc[i][j];
    }
}

// -------- fc reduce --------
__global__ void __launch_bounds__(256) k_fc_red(const float* __restrict__ b_mu,
                                                const float* __restrict__ b_lv,
                                                float* __restrict__ out_mu,
                                                float* __restrict__ out_lv) {
    const int idx = blockIdx.x*256 + threadIdx.x;
    const int n = idx >> 7, o = idx & 127;
    float a = 0.f;
    #pragma unroll
    for (int s2 = 0; s2 < KSPLIT; s2++) a += g_fcp[s2][n][o];
    if (o < 64) out_mu[n*64 + o]      = a + __ldg(b_mu + o);
    else        out_lv[n*64 + (o-64)] = a + __ldg(b_lv + (o-64));
}

// -------- gating --------
__global__ void __launch_bounds__(128) k_gate(
        const float* __restrict__ gw1, const float* __restrict__ gb1,
        const float* __restrict__ gw2, const float* __restrict__ gb2,
        const float* __restrict__ gw3, const float* __restrict__ gb3,
        const float* __restrict__ eps,
        const float* __restrict__ mu_o, const float* __restrict__ lv_o,
        float* __restrict__ logit_o, float* __restrict__ prob_o) {
    __shared__ float sw1[64*64], sw2[64*32], sw3[32*8];
    __shared__ float sb1[64], sb2[32], sb3[8];
    __shared__ float sz[4][64], sh1[4][64], sh2[4][32], sh3[4][8];
    const int tid = threadIdx.x;
    for (int i = tid; i < 4096; i += 128) sw1[i] = gw1[i];
    for (int i = tid; i < 2048; i += 128) sw2[i] = gw2[i];
    for (int i = tid; i < 256;  i += 128) sw3[i] = gw3[i];
    if (tid < 64) sb1[tid] = gb1[tid];
    if (tid < 32) sb2[tid] = gb2[tid];
    if (tid < 8)  sb3[tid] = gb3[tid];
    __syncthreads();
    const int wid = tid >> 5, lane = tid & 31;
    const int n = blockIdx.x*4 + wid;
    for (int o = lane; o < 64; o += 32) {
        float mu = mu_o[n*64+o], lv = lv_o[n*64+o];
        float z = mu + eps[n*64+o]*expf(0.5f*lv);
        g_z[n*64+o] = z; sz[wid][o] = z;
    }
    __syncwarp();
    for (int o = lane; o < 64; o += 32) {
        float a = sb1[o];
        #pragma unroll 8
        for (int k = 0; k < 64; k++) a = fmaf(sz[wid][k], sw1[k*64+o], a);
        sh1[wid][o] = fmaxf(a, 0.f);
    }
    __syncwarp();
    {
        float a = sb2[lane];
        #pragma unroll 8
        for (int k = 0; k < 64; k++) a = fmaf(sh1[wid][k], sw2[k*32+lane], a);
        sh2[wid][lane] = fmaxf(a, 0.f);
    }
    __syncwarp();
    if (lane < 8) {
        float a = sb3[lane];
        #pragma unroll 8
        for (int k = 0; k < 32; k++) a = fmaf(sh2[wid][k], sw3[k*8+lane], a);
        sh3[wid][lane] = a;
    }
    __syncwarp();
    if (lane == 0) {
        float m = sh3[wid][0];
        #pragma unroll
        for (int j = 1; j < 8; j++) m = fmaxf(m, sh3[wid][j]);
        float ex[8], ssum = 0.f;
        #pragma unroll
        for (int j = 0; j < 8; j++) { ex[j] = expf(sh3[wid][j]-m); ssum += ex[j]; }
        const float inv = 1.f/ssum;
        int best = 0; float bp = -1.f;
        #pragma unroll
        for (int j = 0; j < 8; j++) {
            float pp = ex[j]*inv;
            prob_o[n*8+j]  = pp;
            logit_o[n*8+j] = logf(pp + 1e-8f);
            if (pp > bp) { bp = pp; best = j; }
        }
        g_expert[n] = best;
    }
}

// -------- decoder fc --------
__global__ void __launch_bounds__(256) k_dfc(const float* __restrict__ fcw,
                                             const float* __restrict__ fcb) {
    __shared__ float sz[64];
    const int n = blockIdx.x, tid = threadIdx.x;
    const int e = g_expert[n];
    if (tid < 64) sz[tid] = g_z[n*64+tid];
    __syncthreads();
    const float* __restrict__ W  = fcw + (size_t)e*64*1568;
    const float* __restrict__ bb = fcb + (size_t)e*1568;
    for (int o = tid; o < 1568; o += 256) {
        float a = __ldg(bb + o);
        #pragma unroll 8
        for (int k = 0; k < 64; k++) a = fmaf(sz[k], __ldg(W + k*1568 + o), a);
        g_fc[(size_t)n*1568 + o] = a;
    }
}

// -------- decoder conv1 + fused up2 (scalar) --------
__global__ void __launch_bounds__(256) k_dec1(const float* __restrict__ w,
                                              const float* __restrict__ b) {
    __shared__ float s[32*81];
    const int n = blockIdx.x, tid = threadIdx.x;
    const int e = g_expert[n];
    const float* __restrict__ src = g_fc + (size_t)n*1568;
    for (int i = tid; i < 32*81; i += 256) {
        int ic = i/81, rem = i - ic*81, y = rem/9, xx = rem - y*9;
        float v = 0.f;
        if (y >= 1 && y <= 7 && xx >= 1 && xx <= 7) v = src[ic*49 + (y-1)*7 + (xx-1)];
        s[i] = v;
    }
    __syncthreads();
    const int oc = tid & 63, q = tid >> 6;
    const int py = q >> 1, px = q & 1;
    float acc[49];
    const float bias = __ldg(b + e*64 + oc);
    #pragma unroll
    for (int i = 0; i < 49; i++) acc[i] = bias;
    const float* __restrict__ wp = w + ((size_t)e*64 + oc)*32*9;
    for (int ic = 0; ic < 32; ic++) {
        float wr[9];
        #pragma unroll
        for (int k = 0; k < 9; k++) wr[k] = __ldg(wp + ic*9 + k);
        float v0[3], v1[3];
        #pragma unroll
        for (int kx = 0; kx < 3; kx++) {
            v0[kx] = py ? wr[kx]+wr[3+kx] : wr[kx];
            v1[kx] = py ? wr[6+kx]        : wr[3+kx]+wr[6+kx];
        }
        const float e00 = px ? v0[0]+v0[1] : v0[0];
        const float e01 = px ? v0[2]       : v0[1]+v0[2];
        const float e10 = px ? v1[0]+v1[1] : v1[0];
        const float e11 = px ? v1[2]       : v1[1]+v1[2];
        const float* sp = s + ic*81 + py*9 + px;
        #pragma unroll
        for (int r = 0; r < 7; r++) {
            const float* rp = sp + r*9;
            #pragma unroll
            for (int c = 0; c < 7; c++) {
                float a = acc[r*7+c];
                a = fmaf(e00, rp[c],    a);
                a = fmaf(e01, rp[c+1],  a);
                a = fmaf(e10, rp[9+c],  a);
                a = fmaf(e11, rp[10+c], a);
                acc[r*7+c] = a;
            }
        }
    }
    float* __restrict__ op = g_d1 + ((size_t)n*64 + oc)*196;
    #pragma unroll
    for (int r = 0; r < 7; r++)
        #pragma unroll
        for (int c = 0; c < 7; c++) {
            float a = acc[r*7+c];
            op[(2*r+py)*14 + (2*c+px)] = a > 0.f ? a : expm1f(a);
        }
}

// -------- decoder conv2 + fused up2 (scalar, ic-chunked x2) --------
__global__ void __launch_bounds__(256) k_dec2(const float* __restrict__ w,
                                              const float* __restrict__ b) {
    extern __shared__ float s[];                 // 32*256 input + 32*9*32 weights
    float* ws = s + 32*256;
    const int n = blockIdx.x, tid = threadIdx.x;
    const int e = g_expert[n];
    const float* __restrict__ src  = g_d1 + (size_t)n*64*196;
    const float* __restrict__ wsrc = w + (size_t)e*32*64*9;
    const int oc = tid & 31, g = tid >> 5;
    const int q = g & 3, rh = g >> 2;
    const int py = q >> 1, px = q & 1;
    float acc[98];
    const float bias = __ldg(b + e*32 + oc);
    #pragma unroll
    for (int i = 0; i < 98; i++) acc[i] = bias;
    for (int ch = 0; ch < 2; ch++) {
        const int icbase = ch*32;
        if (ch) __syncthreads();
        for (int i = tid; i < 32*256; i += 256) {
            int icl = i >> 8, rem = i & 255, y = rem >> 4, xx = rem & 15;
            float v = 0.f;
            if (y >= 1 && y <= 14 && xx >= 1 && xx <= 14)
                v = src[(icbase+icl)*196 + (y-1)*14 + (xx-1)];
            s[i] = v;
        }
        for (int i = tid; i < 32*32*9; i += 256) {
            int ocl = i/288, rem = i - ocl*288, icl = rem/9, k = rem - icl*9;
            ws[(icl*9+k)*32 + ocl] = wsrc[ocl*576 + (icbase+icl)*9 + k];
        }
        __syncthreads();
        for (int icl = 0; icl < 32; icl++) {
            float wr[9];
            #pragma unroll
            for (int k = 0; k < 9; k++) wr[k] = ws[(icl*9+k)*32 + oc];
            float v0[3], v1[3];
            #pragma unroll
            for (int kx = 0; kx < 3; kx++) {
                v0[kx] = py ? wr[kx]+wr[3+kx] : wr[kx];
                v1[kx] = py ? wr[6+kx]        : wr[3+kx]+wr[6+kx];
            }
            const float e00 = px ? v0[0]+v0[1] : v0[0];
            const float e01 = px ? v0[2]       : v0[1]+v0[2];
            const float e10 = px ? v1[0]+v1[1] : v1[0];
            const float e11 = px ? v1[2]       : v1[1]+v1[2];
            const float* sp = s + icl*256 + (rh*7 + py)*16 + px;
            #pragma unroll
            for (int rr = 0; rr < 7; rr++) {
                const float* rp = sp + rr*16;
                #pragma unroll
                for (int c = 0; c < 14; c++) {
                    float a = acc[rr*14+c];
                    a = fmaf(e00, rp[c],    a);
                    a = fmaf(e01, rp[c+1],  a);
                    a = fmaf(e10, rp[16+c], a);
                    a = fmaf(e11, rp[17+c], a);
                    acc[rr*14+c] = a;
                }
            }
        }
    }
    float* __restrict__ op = g_d2 + ((size_t)n*32 + oc)*784;
    #pragma unroll
    for (int rr = 0; rr < 7; rr++) {
        const int oy = 2*(rh*7+rr) + py;
        #pragma unroll
        for (int c = 0; c < 14; c++) {
            float a = acc[rr*14+c];
            op[oy*28 + 2*c + px] = a > 0.f ? a : expm1f(a);
        }
    }
}

// -------- decoder conv3: 32->1, 28x28, sigmoid (ic-chunked smem) --------
__global__ void __launch_bounds__(256) k_dec3(const float* __restrict__ w,
                                              const float* __restrict__ b,
                                              float* __restrict__ rec) {
    __shared__ float sw[32*9];
    __shared__ float sbb;
    __shared__ float st[8*900];
    const int n = blockIdx.x, tid = threadIdx.x;
    const int e = g_expert[n];
    for (int i = tid; i < 288; i += 256) sw[i] = w[e*288 + i];
    if (tid == 0)  sbb = b[e];
    __syncthreads();
    const float* __restrict__ src = g_d2 + (size_t)n*32*784;
    int oy[4], ox[4];
    float acc[4];
    #pragma unroll
    for (int it = 0; it < 4; it++) {
        int p = tid + 256*it;
        oy[it] = p/28; ox[it] = p - oy[it]*28;
        acc[it] = sbb;
    }
    for (int ch = 0; ch < 4; ch++) {
        const int icb = ch*8;
        if (ch) __syncthreads();
        for (int i = tid; i < 8*900; i += 256) {
            int icl = i/900, rem = i - icl*900, y = rem/30, xx = rem - y*30;
            float v = 0.f;
            if (y >= 1 && y <= 28 && xx >= 1 && xx <= 28)
                v = src[(icb+icl)*784 + (y-1)*28 + (xx-1)];
            st[i] = v;
        }
        __syncthreads();
        for (int icl = 0; icl < 8; icl++) {
            const float* wr = sw + (icb+icl)*9;
            const float w0 = wr[0], w1 = wr[1], w2 = wr[2];
            const float w3 = wr[3], w4 = wr[4], w5 = wr[5];
            const float w6 = wr[6], w7 = wr[7], w8 = wr[8];
            const float* tb = st + icl*900;
            #pragma unroll
            for (int it = 0; it < 4; it++) {
                if (it == 3 && tid >= 16) break;
                const float* sp = tb + oy[it]*30 + ox[it];
                float a = acc[it];
                a = fmaf(w0, sp[0],  a); a = fmaf(w1, sp[1],  a); a = fmaf(w2, sp[2],  a);
                a = fmaf(w3, sp[30], a); a = fmaf(w4, sp[31], a); a = fmaf(w5, sp[32], a);
                a = fmaf(w6, sp[60], a); a = fmaf(w7, sp[61], a); a = fmaf(w8, sp[62], a);
                acc[it] = a;
            }
        }
    }
    #pragma unroll
    for (int it = 0; it < 4; it++) {
        int p = tid + 256*it;
        if (p < 784)
            rec[(size_t)n*784 + p] = 1.f/(1.f + expf(-acc[it]));
    }
}

extern "C" void kernel_launch(void* const* d_in, const int* in_sizes, int n_in,
                              void* d_out, int out_size) {
    const float* x      = (const float*)d_in[0];
    const float* eps    = (const float*)d_in[1];
    const float* enc_w1 = (const float*)d_in[2];
    const float* enc_b1 = (const float*)d_in[3];
    const float* enc_w2 = (const float*)d_in[4];
    const float* enc_b2 = (const float*)d_in[5];
    const float* enc_w3 = (const float*)d_in[6];
    const float* enc_b3 = (const float*)d_in[7];
    const float* w_mu   = (const float*)d_in[8];
    const float* b_mu   = (const float*)d_in[9];
    const float* w_lv   = (const float*)d_in[10];
    const float* b_lv   = (const float*)d_in[11];
    const float* gw1    = (const float*)d_in[12];
    const float* gb1    = (const float*)d_in[13];
    const float* gw2    = (const float*)d_in[14];
    const float* gb2    = (const float*)d_in[15];
    const float* gw3    = (const float*)d_in[16];
    const float* gb3    = (const float*)d_in[17];
    const float* d_fc_w = (const float*)d_in[18];
    const float* d_fc_b = (const float*)d_in[19];
    const float* d_w1   = (const float*)d_in[20];
    const float* d_b1   = (const float*)d_in[21];
    const float* d_w2   = (const float*)d_in[22];
    const float* d_b2   = (const float*)d_in[23];
    const float* d_w3   = (const float*)d_in[24];
    const float* d_b3   = (const float*)d_in[25];

    float* out        = (float*)d_out;
    float* out_rec    = out;
    float* out_mu     = out + 2048*784;
    float* out_lv     = out_mu + 2048*64;
    float* out_logits = out_lv + 2048*64;
    float* out_probs  = out_logits + 2048*8;

    static int attr_done = 0;
    if (!attr_done) {
        cudaFuncSetAttribute(k_enc2, cudaFuncAttributeMaxDynamicSharedMemorySize, 16*900*4);
        cudaFuncSetAttribute(k_enc3, cudaFuncAttributeMaxDynamicSharedMemorySize, 32*256*4);
        cudaFuncSetAttribute(k_dec2, cudaFuncAttributeMaxDynamicSharedMemorySize, (32*256 + 32*9*32)*4);
        attr_done = 1;
    }

    k_enc1<<<BATCH, 256>>>(x, enc_w1, enc_b1);
    k_enc2<<<BATCH, 256, 16*900*4>>>(enc_w2, enc_b2);
    k_enc3<<<BATCH, 128, 32*256*4>>>(enc_w3, enc_b3);
    k_fc_part<<<128*KSPLIT, 256>>>(w_mu, w_lv);
    k_fc_red <<<BATCH*128/256, 256>>>(b_mu, b_lv, out_mu, out_lv);
    k_gate<<<BATCH/4, 128>>>(gw1, gb1, gw2, gb2, gw3, gb3, eps,
                             out_mu, out_lv, out_logits, out_probs);
    k_dfc <<<BATCH, 256>>>(d_fc_w, d_fc_b);
    k_dec1<<<BATCH, 256>>>(d_w1, d_b1);
    k_dec2<<<BATCH, 256, (32*256 + 32*9*32)*4>>>(d_w2, d_b2);
    k_dec3<<<BATCH, 256>>>(d_w3, d_b3, out_rec);
}